// round 3
// baseline (speedup 1.0000x reference)
#include <cuda_runtime.h>

#define DD   256
#define HID  1024
#define NL   4
#define NB   16
#define SEQ  4096
#define NC   10
#define NBLK 128

__device__ float g_h[NB * DD];
__device__ float g_v[NB * DD];
__device__ float g_hid[NB * HID];
__device__ unsigned g_flags[NBLK];
__device__ unsigned g_gen;

__device__ __forceinline__ float gelu_tanh(float x) {
    const float k0 = 0.7978845608028654f;   // sqrt(2/pi)
    float x3 = x * x * x;
    return 0.5f * x * (1.0f + tanhf(k0 * (x + 0.044715f * x3)));
}

// Grid barrier: blocks 1..127 write per-block flags (no atomic contention);
// block 0 polls all flags then publishes the generation. ep is monotonically
// increasing across graph replays (seeded from g_gen at kernel entry).
__device__ __forceinline__ void gbar(unsigned ep) {
    __threadfence();
    __syncthreads();
    if (blockIdx.x == 0) {
        int t = threadIdx.x;
        if (t >= 1 && t < NBLK) {
            while (((volatile unsigned*)g_flags)[t] < ep) __nanosleep(32);
        }
        __syncthreads();
        if (t == 0) {
            __threadfence();
            ((volatile unsigned*)&g_gen)[0] = ep;
        }
    } else {
        if (threadIdx.x == 0) {
            ((volatile unsigned*)g_flags)[blockIdx.x] = ep;
            while (((volatile unsigned*)&g_gen)[0] < ep) __nanosleep(32);
        }
    }
    __threadfence();
    __syncthreads();
}

struct Sh {
    float  y[DD];
    float4 ps[256];
    float4 ps2[64];
    float4 hid4[DD];
    float  warp[16];
    float  stat[2];
};

// LayerNorm of g_h[b] (one element per thread) -> sh->y
__device__ __forceinline__ void block_ln(
    float hval, const float* __restrict__ lns, const float* __restrict__ lnb,
    Sh* sh, int t)
{
    int lane = t & 31, wid = t >> 5;
    float s1 = hval, s2 = hval * hval;
#pragma unroll
    for (int o = 16; o; o >>= 1) {
        s1 += __shfl_xor_sync(0xffffffffu, s1, o);
        s2 += __shfl_xor_sync(0xffffffffu, s2, o);
    }
    if (lane == 0) { sh->warp[wid] = s1; sh->warp[8 + wid] = s2; }
    __syncthreads();
    if (t == 0) {
        float a = 0.f, c = 0.f;
#pragma unroll
        for (int i = 0; i < 8; ++i) { a += sh->warp[i]; c += sh->warp[8 + i]; }
        float mu = a * (1.0f / DD);
        float var = c * (1.0f / DD) - mu * mu;
        sh->stat[0] = mu;
        sh->stat[1] = rsqrtf(fmaxf(var, 0.f) + 1e-5f);
    }
    __syncthreads();
    sh->y[t] = (hval - sh->stat[0]) * sh->stat[1] * lns[t] + lnb[t];
    __syncthreads();
}

__global__ __launch_bounds__(256, 1) void perf_persist(
    const int*   __restrict__ x,
    const float* __restrict__ emb_tok,
    const float* __restrict__ emb_pos,
    const float* __restrict__ ln1_s, const float* __restrict__ ln1_b,
    const float* __restrict__ wv,    const float* __restrict__ wo,
    const float* __restrict__ bo,
    const float* __restrict__ ln2_s, const float* __restrict__ ln2_b,
    const float* __restrict__ w1,    const float* __restrict__ b1,
    const float* __restrict__ w2,    const float* __restrict__ b2,
    const float* __restrict__ w_cls, const float* __restrict__ b_cls,
    float* __restrict__ out)
{
    __shared__ Sh sh;
    const int bk = blockIdx.x, t = threadIdx.x;
    const int lane = t & 31, w = t >> 5;

    unsigned ep = ((volatile unsigned*)&g_gen)[0];

    // ---------------- init: h[b] = emb_tok[x[b,0]] + emb_pos[0] ----------------
    if (bk < NB) {
        int tok = x[bk * SEQ];
        g_h[bk * DD + t] = emb_tok[tok * DD + t] + emb_pos[t];
    }
    gbar(++ep);

    for (int l = 0; l < NL; ++l) {
        // ============ wv: v = LN1(h) @ wv   (64 blocks: 16 b x 4 quad-groups) ============
        if (bk < 64) {
            int b = bk >> 2, qq = bk & 3;
            const float4* W4 = (const float4*)(wv + (size_t)l * DD * DD); // [256][64]
            int q16 = lane & 15, rh = lane >> 4;
            int jq = qq * 16 + q16;
            int r0 = w * 32 + rh * 16;
            float4 wr[16];
#pragma unroll
            for (int i = 0; i < 16; ++i) wr[i] = W4[(r0 + i) * 64 + jq];

            block_ln(g_h[b * DD + t], ln1_s + l * DD, ln1_b + l * DD, &sh, t);

            float4 acc = make_float4(0.f, 0.f, 0.f, 0.f);
#pragma unroll
            for (int i = 0; i < 16; ++i) {
                float yv = sh.y[r0 + i];
                acc.x += yv * wr[i].x; acc.y += yv * wr[i].y;
                acc.z += yv * wr[i].z; acc.w += yv * wr[i].w;
            }
            sh.ps[(w * 2 + rh) * 16 + q16] = acc;
            __syncthreads();
            if (t < 16) {
                float4 a = sh.ps[t];
#pragma unroll
                for (int s = 1; s < 16; ++s) {
                    float4 r = sh.ps[s * 16 + t];
                    a.x += r.x; a.y += r.y; a.z += r.z; a.w += r.w;
                }
                ((float4*)(g_v + b * DD))[qq * 16 + t] = a;
            }
        }
        gbar(++ep);

        // ============ wo: h += v @ wo + bo   (64 blocks) ============
        if (bk < 64) {
            int b = bk >> 2, qq = bk & 3;
            const float4* W4 = (const float4*)(wo + (size_t)l * DD * DD);
            int q16 = lane & 15, rh = lane >> 4;
            int jq = qq * 16 + q16;
            int r0 = w * 32 + rh * 16;
            float4 wr[16];
#pragma unroll
            for (int i = 0; i < 16; ++i) wr[i] = W4[(r0 + i) * 64 + jq];

            sh.y[t] = g_v[b * DD + t];
            __syncthreads();

            float4 acc = make_float4(0.f, 0.f, 0.f, 0.f);
#pragma unroll
            for (int i = 0; i < 16; ++i) {
                float yv = sh.y[r0 + i];
                acc.x += yv * wr[i].x; acc.y += yv * wr[i].y;
                acc.z += yv * wr[i].z; acc.w += yv * wr[i].w;
            }
            sh.ps[(w * 2 + rh) * 16 + q16] = acc;
            __syncthreads();
            if (t < 16) {
                float4 a = sh.ps[t];
#pragma unroll
                for (int s = 1; s < 16; ++s) {
                    float4 r = sh.ps[s * 16 + t];
                    a.x += r.x; a.y += r.y; a.z += r.z; a.w += r.w;
                }
                float4 ho = ((const float4*)(g_h + b * DD))[qq * 16 + t];
                float4 bb = ((const float4*)(bo + l * DD))[qq * 16 + t];
                a.x += ho.x + bb.x; a.y += ho.y + bb.y;
                a.z += ho.z + bb.z; a.w += ho.w + bb.w;
                ((float4*)(g_h + b * DD))[qq * 16 + t] = a;
            }
        }
        gbar(++ep);

        // ============ up: hid = gelu(LN2(h) @ w1 + b1)   (128 blocks: 16 b x 8 octs) ============
        {
            int b = bk >> 3, o8 = bk & 7;
            const float4* W14 = (const float4*)(w1 + (size_t)l * DD * HID); // [256][256]
            int jq = o8 * 32 + lane;
            int r0 = w * 32;
            float4 wr[16];
#pragma unroll
            for (int i = 0; i < 16; ++i) wr[i] = W14[(r0 + i) * 256 + jq];

            block_ln(g_h[b * DD + t], ln2_s + l * DD, ln2_b + l * DD, &sh, t);

            float4 acc = make_float4(0.f, 0.f, 0.f, 0.f);
#pragma unroll
            for (int i = 0; i < 16; ++i) {
                float yv = sh.y[r0 + i];
                acc.x += yv * wr[i].x; acc.y += yv * wr[i].y;
                acc.z += yv * wr[i].z; acc.w += yv * wr[i].w;
            }
#pragma unroll
            for (int i = 0; i < 16; ++i) wr[i] = W14[(r0 + 16 + i) * 256 + jq];
#pragma unroll
            for (int i = 0; i < 16; ++i) {
                float yv = sh.y[r0 + 16 + i];
                acc.x += yv * wr[i].x; acc.y += yv * wr[i].y;
                acc.z += yv * wr[i].z; acc.w += yv * wr[i].w;
            }
            sh.ps[w * 32 + lane] = acc;
            __syncthreads();
            if (t < 32) {
                float4 a = sh.ps[t];
#pragma unroll
                for (int s = 1; s < 8; ++s) {
                    float4 r = sh.ps[s * 32 + t];
                    a.x += r.x; a.y += r.y; a.z += r.z; a.w += r.w;
                }
                float4 bb = ((const float4*)(b1 + l * HID))[o8 * 32 + t];
                float4 g;
                g.x = gelu_tanh(a.x + bb.x);
                g.y = gelu_tanh(a.y + bb.y);
                g.z = gelu_tanh(a.z + bb.z);
                g.w = gelu_tanh(a.w + bb.w);
                ((float4*)(g_hid + b * HID))[o8 * 32 + t] = g;
            }
        }
        gbar(++ep);

        // ============ down: h += hid @ w2 + b2   (128 blocks: 16 b x 8 quad-groups) ============
        {
            int b = bk >> 3, g8 = bk & 7;
            const float4* W24 = (const float4*)(w2 + (size_t)l * HID * DD); // [1024][64]
            int q8 = lane & 7, rs = lane >> 3;          // rs 0..3
            int jq = g8 * 8 + q8;
            int r0 = (w * 4 + rs) * 32;                 // 32 rows per thread
            float4 wr[16];
#pragma unroll
            for (int i = 0; i < 16; ++i) wr[i] = W24[(r0 + i) * 64 + jq];

            sh.hid4[t] = ((const float4*)(g_hid + b * HID))[t];
            __syncthreads();
            const float* shid = (const float*)sh.hid4;

            float4 acc = make_float4(0.f, 0.f, 0.f, 0.f);
#pragma unroll
            for (int i = 0; i < 16; ++i) {
                float hv = shid[r0 + i];
                acc.x += hv * wr[i].x; acc.y += hv * wr[i].y;
                acc.z += hv * wr[i].z; acc.w += hv * wr[i].w;
            }
#pragma unroll
            for (int i = 0; i < 16; ++i) wr[i] = W24[(r0 + 16 + i) * 64 + jq];
#pragma unroll
            for (int i = 0; i < 16; ++i) {
                float hv = shid[r0 + 16 + i];
                acc.x += hv * wr[i].x; acc.y += hv * wr[i].y;
                acc.z += hv * wr[i].z; acc.w += hv * wr[i].w;
            }
            sh.ps[(w * 4 + rs) * 8 + q8] = acc;        // [32 segs][8 quads]
            __syncthreads();
            if (t < 64) {
                int sub = t >> 3, q = t & 7;
                float4 a = sh.ps[(sub * 4) * 8 + q];
#pragma unroll
                for (int k = 1; k < 4; ++k) {
                    float4 r = sh.ps[(sub * 4 + k) * 8 + q];
                    a.x += r.x; a.y += r.y; a.z += r.z; a.w += r.w;
                }
                sh.ps2[sub * 8 + q] = a;
            }
            __syncthreads();
            if (t < 8) {
                float4 a = sh.ps2[t];
#pragma unroll
                for (int s = 1; s < 8; ++s) {
                    float4 r = sh.ps2[s * 8 + t];
                    a.x += r.x; a.y += r.y; a.z += r.z; a.w += r.w;
                }
                float4 bb = ((const float4*)(b2 + l * DD))[g8 * 8 + t];
                float4 ho = ((const float4*)(g_h + b * DD))[g8 * 8 + t];
                a.x += bb.x + ho.x; a.y += bb.y + ho.y;
                a.z += bb.z + ho.z; a.w += bb.w + ho.w;
                ((float4*)(g_h + b * DD))[g8 * 8 + t] = a;
            }
        }
        gbar(++ep);
    }

    // ---------------- head: out[b,c] = h[b] . w_cls[:,c] + b_cls[c] ----------------
    if (bk < NB) {
        sh.y[t] = g_h[bk * DD + t];
        __syncthreads();
        if (t < NC) {
            float acc = b_cls[t];
#pragma unroll 8
            for (int d = 0; d < DD; ++d)
                acc += sh.y[d] * w_cls[d * NC + t];
            out[bk * NC + t] = acc;
        }
    }
}

extern "C" void kernel_launch(void* const* d_in, const int* in_sizes, int n_in,
                              void* d_out, int out_size)
{
    // 0:x 1:emb_tok 2:emb_pos 3:proj 4:ln1_s 5:ln1_b 6:wq 7:wk 8:wv 9:wo
    // 10:bo 11:ln2_s 12:ln2_b 13:w1 14:b1 15:w2 16:b2 17:w_cls 18:b_cls
    const int*   x       = (const int*)  d_in[0];
    const float* emb_tok = (const float*)d_in[1];
    const float* emb_pos = (const float*)d_in[2];
    const float* ln1_s   = (const float*)d_in[4];
    const float* ln1_b   = (const float*)d_in[5];
    const float* wv      = (const float*)d_in[8];
    const float* wo      = (const float*)d_in[9];
    const float* bo      = (const float*)d_in[10];
    const float* ln2_s   = (const float*)d_in[11];
    const float* ln2_b   = (const float*)d_in[12];
    const float* w1      = (const float*)d_in[13];
    const float* b1      = (const float*)d_in[14];
    const float* w2      = (const float*)d_in[15];
    const float* b2      = (const float*)d_in[16];
    const float* w_cls   = (const float*)d_in[17];
    const float* b_cls   = (const float*)d_in[18];
    float* out = (float*)d_out;

    perf_persist<<<NBLK, 256>>>(x, emb_tok, emb_pos, ln1_s, ln1_b,
                                wv, wo, bo, ln2_s, ln2_b,
                                w1, b1, w2, b2, w_cls, b_cls, out);
}

// round 4
// speedup vs baseline: 1.3116x; 1.3116x over previous
#include <cuda_runtime.h>

#define DD   256
#define HID  1024
#define NL   4
#define NB   16
#define SEQ  4096
#define NC   10

__device__ float g_h[NB * DD];
__device__ float g_v[NB * DD];
__device__ float g_hid[NB * HID];

__device__ __forceinline__ float gelu_tanh(float x) {
    const float k0 = 0.7978845608028654f;   // sqrt(2/pi)
    float x3 = x * x * x;
    return 0.5f * x * (1.0f + tanhf(k0 * (x + 0.044715f * x3)));
}

// Block-wide LayerNorm of a 256-vector (one value per thread) -> sh_y.
__device__ __forceinline__ void block_ln(
    float hval, const float* __restrict__ lns, const float* __restrict__ lnb,
    float* sh_y, float* sh_warp, float* sh_stat, int t)
{
    int lane = t & 31, wid = t >> 5;
    float s1 = hval, s2 = hval * hval;
#pragma unroll
    for (int o = 16; o; o >>= 1) {
        s1 += __shfl_xor_sync(0xffffffffu, s1, o);
        s2 += __shfl_xor_sync(0xffffffffu, s2, o);
    }
    if (lane == 0) { sh_warp[wid] = s1; sh_warp[8 + wid] = s2; }
    __syncthreads();
    if (t == 0) {
        float a = 0.f, c = 0.f;
#pragma unroll
        for (int i = 0; i < 8; ++i) { a += sh_warp[i]; c += sh_warp[8 + i]; }
        float mu = a * (1.0f / DD);
        float var = c * (1.0f / DD) - mu * mu;
        sh_stat[0] = mu;
        sh_stat[1] = rsqrtf(fmaxf(var, 0.f) + 1e-5f);
    }
    __syncthreads();
    sh_y[t] = (hval - sh_stat[0]) * sh_stat[1] * lns[t] + lnb[t];
    __syncthreads();
}

// ============ K1: v = LN1(h) @ wv.  grid 64 = 16 b x 4 quad-groups ============
// first!=0: h computed from embeddings in-kernel (layer 0), qq==0 block persists it.
__global__ __launch_bounds__(256) void k_attn_v(
    const float* __restrict__ W, const float* __restrict__ lns,
    const float* __restrict__ lnb, int first,
    const int* __restrict__ x, const float* __restrict__ emb_tok,
    const float* __restrict__ emb_pos)
{
    __shared__ float  sh_y[DD];
    __shared__ float4 sh_ps[256];
    __shared__ float  sh_warp[16], sh_stat[2];
    int bk = blockIdx.x, t = threadIdx.x;
    int lane = t & 31, w = t >> 5;
    int b = bk >> 2, qq = bk & 3;

    const float4* W4 = (const float4*)W;   // [256 rows][64 quads]
    int q16 = lane & 15, rh = lane >> 4;
    int jq = qq * 16 + q16;
    int r0 = w * 32 + rh * 16;
    float4 wr[16];
#pragma unroll
    for (int i = 0; i < 16; ++i) wr[i] = W4[(r0 + i) * 64 + jq];

    float hval;
    if (first) {
        int tok = x[b * SEQ];
        hval = emb_tok[tok * DD + t] + emb_pos[t];
        if (qq == 0) g_h[b * DD + t] = hval;
    } else {
        hval = g_h[b * DD + t];
    }
    block_ln(hval, lns, lnb, sh_y, sh_warp, sh_stat, t);

    float4 acc = make_float4(0.f, 0.f, 0.f, 0.f);
#pragma unroll
    for (int i = 0; i < 16; ++i) {
        float yv = sh_y[r0 + i];
        acc.x += yv * wr[i].x; acc.y += yv * wr[i].y;
        acc.z += yv * wr[i].z; acc.w += yv * wr[i].w;
    }
    sh_ps[(w * 2 + rh) * 16 + q16] = acc;
    __syncthreads();
    if (t < 16) {
        float4 a = sh_ps[t];
#pragma unroll
        for (int s = 1; s < 16; ++s) {
            float4 r = sh_ps[s * 16 + t];
            a.x += r.x; a.y += r.y; a.z += r.z; a.w += r.w;
        }
        ((float4*)(g_v + b * DD))[qq * 16 + t] = a;
    }
}

// ============ K2: h += v @ wo + bo.  grid 64 ============
__global__ __launch_bounds__(256) void k_attn_o(
    const float* __restrict__ W, const float* __restrict__ bo)
{
    __shared__ float  sh_y[DD];
    __shared__ float4 sh_ps[256];
    int bk = blockIdx.x, t = threadIdx.x;
    int lane = t & 31, w = t >> 5;
    int b = bk >> 2, qq = bk & 3;

    const float4* W4 = (const float4*)W;
    int q16 = lane & 15, rh = lane >> 4;
    int jq = qq * 16 + q16;
    int r0 = w * 32 + rh * 16;
    float4 wr[16];
#pragma unroll
    for (int i = 0; i < 16; ++i) wr[i] = W4[(r0 + i) * 64 + jq];

    sh_y[t] = g_v[b * DD + t];
    __syncthreads();

    float4 acc = make_float4(0.f, 0.f, 0.f, 0.f);
#pragma unroll
    for (int i = 0; i < 16; ++i) {
        float yv = sh_y[r0 + i];
        acc.x += yv * wr[i].x; acc.y += yv * wr[i].y;
        acc.z += yv * wr[i].z; acc.w += yv * wr[i].w;
    }
    sh_ps[(w * 2 + rh) * 16 + q16] = acc;
    __syncthreads();
    if (t < 16) {
        float4 a = sh_ps[t];
#pragma unroll
        for (int s = 1; s < 16; ++s) {
            float4 r = sh_ps[s * 16 + t];
            a.x += r.x; a.y += r.y; a.z += r.z; a.w += r.w;
        }
        float4 ho = ((const float4*)(g_h + b * DD))[qq * 16 + t];
        float4 bb = ((const float4*)bo)[qq * 16 + t];
        a.x += ho.x + bb.x; a.y += ho.y + bb.y;
        a.z += ho.z + bb.z; a.w += ho.w + bb.w;
        ((float4*)(g_h + b * DD))[qq * 16 + t] = a;
    }
}

// ============ K3: hid = gelu(LN2(h) @ w1 + b1).  grid 128 = 16 b x 8 octs ============
__global__ __launch_bounds__(256) void k_mlp_up(
    const float* __restrict__ W, const float* __restrict__ bias,
    const float* __restrict__ lns, const float* __restrict__ lnb)
{
    __shared__ float  sh_y[DD];
    __shared__ float4 sh_ps[256];
    __shared__ float  sh_warp[16], sh_stat[2];
    int bk = blockIdx.x, t = threadIdx.x;
    int lane = t & 31, w = t >> 5;
    int b = bk >> 3, o8 = bk & 7;

    const float4* W14 = (const float4*)W;  // [256 rows][256 quads]
    int jq = o8 * 32 + lane;
    int r0 = w * 32;
    float4 wr[16];
#pragma unroll
    for (int i = 0; i < 16; ++i) wr[i] = W14[(r0 + i) * 256 + jq];

    block_ln(g_h[b * DD + t], lns, lnb, sh_y, sh_warp, sh_stat, t);

    float4 acc = make_float4(0.f, 0.f, 0.f, 0.f);
#pragma unroll
    for (int i = 0; i < 16; ++i) {
        float yv = sh_y[r0 + i];
        acc.x += yv * wr[i].x; acc.y += yv * wr[i].y;
        acc.z += yv * wr[i].z; acc.w += yv * wr[i].w;
    }
#pragma unroll
    for (int i = 0; i < 16; ++i) wr[i] = W14[(r0 + 16 + i) * 256 + jq];
#pragma unroll
    for (int i = 0; i < 16; ++i) {
        float yv = sh_y[r0 + 16 + i];
        acc.x += yv * wr[i].x; acc.y += yv * wr[i].y;
        acc.z += yv * wr[i].z; acc.w += yv * wr[i].w;
    }
    sh_ps[w * 32 + lane] = acc;
    __syncthreads();
    if (t < 32) {
        float4 a = sh_ps[t];
#pragma unroll
        for (int s = 1; s < 8; ++s) {
            float4 r = sh_ps[s * 32 + t];
            a.x += r.x; a.y += r.y; a.z += r.z; a.w += r.w;
        }
        float4 bb = ((const float4*)bias)[o8 * 32 + t];
        float4 g;
        g.x = gelu_tanh(a.x + bb.x);
        g.y = gelu_tanh(a.y + bb.y);
        g.z = gelu_tanh(a.z + bb.z);
        g.w = gelu_tanh(a.w + bb.w);
        ((float4*)(g_hid + b * HID))[o8 * 32 + t] = g;
    }
}

// ============ K4: h += hid @ w2 + b2.  grid 128 = 16 b x 8 quad-groups ============
__global__ __launch_bounds__(256) void k_mlp_down(
    const float* __restrict__ W, const float* __restrict__ bias)
{
    __shared__ float4 sh_hid4[DD];      // 1024 floats
    __shared__ float4 sh_ps[256];
    __shared__ float4 sh_ps2[64];
    int bk = blockIdx.x, t = threadIdx.x;
    int lane = t & 31, w = t >> 5;
    int b = bk >> 3, g8 = bk & 7;

    const float4* W24 = (const float4*)W;  // [1024 rows][64 quads]
    int q8 = lane & 7, rs = lane >> 3;     // rs 0..3
    int jq = g8 * 8 + q8;
    int r0 = (w * 4 + rs) * 32;            // 32 rows per thread
    float4 wr[16];
#pragma unroll
    for (int i = 0; i < 16; ++i) wr[i] = W24[(r0 + i) * 64 + jq];

    sh_hid4[t] = ((const float4*)(g_hid + b * HID))[t];
    __syncthreads();
    const float* shid = (const float*)sh_hid4;

    float4 acc = make_float4(0.f, 0.f, 0.f, 0.f);
#pragma unroll
    for (int i = 0; i < 16; ++i) {
        float hv = shid[r0 + i];
        acc.x += hv * wr[i].x; acc.y += hv * wr[i].y;
        acc.z += hv * wr[i].z; acc.w += hv * wr[i].w;
    }
#pragma unroll
    for (int i = 0; i < 16; ++i) wr[i] = W24[(r0 + 16 + i) * 64 + jq];
#pragma unroll
    for (int i = 0; i < 16; ++i) {
        float hv = shid[r0 + 16 + i];
        acc.x += hv * wr[i].x; acc.y += hv * wr[i].y;
        acc.z += hv * wr[i].z; acc.w += hv * wr[i].w;
    }
    sh_ps[(w * 4 + rs) * 8 + q8] = acc;    // [32 segs][8 quads]
    __syncthreads();
    if (t < 64) {
        int sub = t >> 3, q = t & 7;
        float4 a = sh_ps[(sub * 4) * 8 + q];
#pragma unroll
        for (int k = 1; k < 4; ++k) {
            float4 r = sh_ps[(sub * 4 + k) * 8 + q];
            a.x += r.x; a.y += r.y; a.z += r.z; a.w += r.w;
        }
        sh_ps2[sub * 8 + q] = a;
    }
    __syncthreads();
    if (t < 8) {
        float4 a = sh_ps2[t];
#pragma unroll
        for (int s = 1; s < 8; ++s) {
            float4 r = sh_ps2[s * 8 + t];
            a.x += r.x; a.y += r.y; a.z += r.z; a.w += r.w;
        }
        float4 bb = ((const float4*)bias)[g8 * 8 + t];
        float4 ho = ((const float4*)(g_h + b * DD))[g8 * 8 + t];
        a.x += bb.x + ho.x; a.y += bb.y + ho.y;
        a.z += bb.z + ho.z; a.w += bb.w + ho.w;
        ((float4*)(g_h + b * DD))[g8 * 8 + t] = a;
    }
}

// ============ head: out[b,c] = h[b] . w_cls[:,c] + b_cls[c] ============
__global__ __launch_bounds__(256) void k_head(
    const float* __restrict__ w_cls, const float* __restrict__ b_cls,
    float* __restrict__ out)
{
    __shared__ float sh_h[DD];
    int b = blockIdx.x, t = threadIdx.x;
    sh_h[t] = g_h[b * DD + t];
    __syncthreads();
    if (t < NC) {
        float acc = b_cls[t];
#pragma unroll 8
        for (int d = 0; d < DD; ++d)
            acc += sh_h[d] * w_cls[d * NC + t];
        out[b * NC + t] = acc;
    }
}

extern "C" void kernel_launch(void* const* d_in, const int* in_sizes, int n_in,
                              void* d_out, int out_size)
{
    // 0:x 1:emb_tok 2:emb_pos 3:proj 4:ln1_s 5:ln1_b 6:wq 7:wk 8:wv 9:wo
    // 10:bo 11:ln2_s 12:ln2_b 13:w1 14:b1 15:w2 16:b2 17:w_cls 18:b_cls
    const int*   x       = (const int*)  d_in[0];
    const float* emb_tok = (const float*)d_in[1];
    const float* emb_pos = (const float*)d_in[2];
    const float* ln1_s   = (const float*)d_in[4];
    const float* ln1_b   = (const float*)d_in[5];
    const float* wv      = (const float*)d_in[8];
    const float* wo      = (const float*)d_in[9];
    const float* bo      = (const float*)d_in[10];
    const float* ln2_s   = (const float*)d_in[11];
    const float* ln2_b   = (const float*)d_in[12];
    const float* w1      = (const float*)d_in[13];
    const float* b1      = (const float*)d_in[14];
    const float* w2      = (const float*)d_in[15];
    const float* b2      = (const float*)d_in[16];
    const float* w_cls   = (const float*)d_in[17];
    const float* b_cls   = (const float*)d_in[18];
    float* out = (float*)d_out;

    for (int l = 0; l < NL; ++l) {
        size_t oDD = (size_t)l * DD * DD;
        k_attn_v<<<64, 256>>>(wv + oDD, ln1_s + l * DD, ln1_b + l * DD,
                              l == 0 ? 1 : 0, x, emb_tok, emb_pos);
        k_attn_o<<<64, 256>>>(wo + oDD, bo + l * DD);
        k_mlp_up<<<128, 256>>>(w1 + (size_t)l * DD * HID, b1 + l * HID,
                               ln2_s + l * DD, ln2_b + l * DD);
        k_mlp_down<<<128, 256>>>(w2 + (size_t)l * HID * DD, b2 + l * DD);
    }
    k_head<<<NB, 256>>>(w_cls, b_cls, out);
}

// round 5
// speedup vs baseline: 1.4977x; 1.1419x over previous
#include <cuda_runtime.h>

#define DD   256
#define HID  1024
#define NL   4
#define NB   16
#define SEQ  4096
#define NC   10

__device__ float g_h[NB * DD];
__device__ float g_v[NB * DD];
__device__ float g_hid[NB * HID];

__device__ __forceinline__ float gelu_tanh(float x) {
    const float k0 = 0.7978845608028654f;   // sqrt(2/pi)
    float x3 = x * x * x;
    return 0.5f * x * (1.0f + tanhf(k0 * (x + 0.044715f * x3)));
}

// Block-wide LayerNorm of a 256-vector (one value per thread) -> sh_y.
__device__ __forceinline__ void block_ln(
    float hval, const float* __restrict__ lns, const float* __restrict__ lnb,
    float* sh_y, float* sh_warp, float* sh_stat, int t)
{
    int lane = t & 31, wid = t >> 5;
    float s1 = hval, s2 = hval * hval;
#pragma unroll
    for (int o = 16; o; o >>= 1) {
        s1 += __shfl_xor_sync(0xffffffffu, s1, o);
        s2 += __shfl_xor_sync(0xffffffffu, s2, o);
    }
    if (lane == 0) { sh_warp[wid] = s1; sh_warp[8 + wid] = s2; }
    __syncthreads();
    if (t == 0) {
        float a = 0.f, c = 0.f;
#pragma unroll
        for (int i = 0; i < 8; ++i) { a += sh_warp[i]; c += sh_warp[8 + i]; }
        float mu = a * (1.0f / DD);
        float var = c * (1.0f / DD) - mu * mu;
        sh_stat[0] = mu;
        sh_stat[1] = rsqrtf(fmaxf(var, 0.f) + 1e-5f);
    }
    __syncthreads();
    sh_y[t] = (hval - sh_stat[0]) * sh_stat[1] * lns[t] + lnb[t];
    __syncthreads();
}

// ============ K1: v = LN1(h) @ wv.  grid 64 = 16 b x 4 quad-groups ============
// first!=0: h computed from embeddings in-kernel (layer 0), qq==0 block persists it.
__global__ __launch_bounds__(256, 1) void k_attn_v(
    const float* __restrict__ W, const float* __restrict__ lns,
    const float* __restrict__ lnb, int first,
    const int* __restrict__ x, const float* __restrict__ emb_tok,
    const float* __restrict__ emb_pos)
{
    __shared__ float  sh_y[DD];
    __shared__ float4 sh_ps[256];
    __shared__ float  sh_warp[16], sh_stat[2];
    int bk = blockIdx.x, t = threadIdx.x;
    int lane = t & 31, w = t >> 5;
    int b = bk >> 2, qq = bk & 3;

    const float4* W4 = (const float4*)W;   // [256 rows][64 quads]
    int q16 = lane & 15, rh = lane >> 4;
    int jq = qq * 16 + q16;
    int r0 = w * 32 + rh * 16;
    float4 wr[16];
#pragma unroll
    for (int i = 0; i < 16; ++i) wr[i] = W4[(r0 + i) * 64 + jq];

    float hval;
    if (first) {
        int tok = x[b * SEQ];
        hval = emb_tok[tok * DD + t] + emb_pos[t];
        if (qq == 0) g_h[b * DD + t] = hval;
    } else {
        hval = g_h[b * DD + t];
    }
    block_ln(hval, lns, lnb, sh_y, sh_warp, sh_stat, t);

    float4 acc = make_float4(0.f, 0.f, 0.f, 0.f);
#pragma unroll
    for (int i = 0; i < 16; ++i) {
        float yv = sh_y[r0 + i];
        acc.x += yv * wr[i].x; acc.y += yv * wr[i].y;
        acc.z += yv * wr[i].z; acc.w += yv * wr[i].w;
    }
    sh_ps[(w * 2 + rh) * 16 + q16] = acc;
    __syncthreads();
    if (t < 16) {
        float4 a = sh_ps[t];
#pragma unroll
        for (int s = 1; s < 16; ++s) {
            float4 r = sh_ps[s * 16 + t];
            a.x += r.x; a.y += r.y; a.z += r.z; a.w += r.w;
        }
        ((float4*)(g_v + b * DD))[qq * 16 + t] = a;
    }
}

// ============ K2: h += v @ wo + bo.  grid 64 ============
__global__ __launch_bounds__(256, 1) void k_attn_o(
    const float* __restrict__ W, const float* __restrict__ bo)
{
    __shared__ float  sh_y[DD];
    __shared__ float4 sh_ps[256];
    int bk = blockIdx.x, t = threadIdx.x;
    int lane = t & 31, w = t >> 5;
    int b = bk >> 2, qq = bk & 3;

    const float4* W4 = (const float4*)W;
    int q16 = lane & 15, rh = lane >> 4;
    int jq = qq * 16 + q16;
    int r0 = w * 32 + rh * 16;
    float4 wr[16];
#pragma unroll
    for (int i = 0; i < 16; ++i) wr[i] = W4[(r0 + i) * 64 + jq];

    sh_y[t] = g_v[b * DD + t];
    __syncthreads();

    float4 acc = make_float4(0.f, 0.f, 0.f, 0.f);
#pragma unroll
    for (int i = 0; i < 16; ++i) {
        float yv = sh_y[r0 + i];
        acc.x += yv * wr[i].x; acc.y += yv * wr[i].y;
        acc.z += yv * wr[i].z; acc.w += yv * wr[i].w;
    }
    sh_ps[(w * 2 + rh) * 16 + q16] = acc;
    __syncthreads();
    if (t < 16) {
        float4 a = sh_ps[t];
#pragma unroll
        for (int s = 1; s < 16; ++s) {
            float4 r = sh_ps[s * 16 + t];
            a.x += r.x; a.y += r.y; a.z += r.z; a.w += r.w;
        }
        float4 ho = ((const float4*)(g_h + b * DD))[qq * 16 + t];
        float4 bb = ((const float4*)bo)[qq * 16 + t];
        a.x += ho.x + bb.x; a.y += ho.y + bb.y;
        a.z += ho.z + bb.z; a.w += ho.w + bb.w;
        ((float4*)(g_h + b * DD))[qq * 16 + t] = a;
    }
}

// ============ K3: hid = gelu(LN2(h) @ w1 + b1).  grid 128 = 16 b x 8 octs ============
__global__ __launch_bounds__(256, 1) void k_mlp_up(
    const float* __restrict__ W, const float* __restrict__ bias,
    const float* __restrict__ lns, const float* __restrict__ lnb)
{
    __shared__ float  sh_y[DD];
    __shared__ float4 sh_ps[256];
    __shared__ float  sh_warp[16], sh_stat[2];
    int bk = blockIdx.x, t = threadIdx.x;
    int lane = t & 31, w = t >> 5;
    int b = bk >> 3, o8 = bk & 7;

    const float4* W14 = (const float4*)W;  // [256 rows][256 quads]
    int jq = o8 * 32 + lane;
    int r0 = w * 32;
    float4 wr[16];
#pragma unroll
    for (int i = 0; i < 16; ++i) wr[i] = W14[(r0 + i) * 256 + jq];

    block_ln(g_h[b * DD + t], lns, lnb, sh_y, sh_warp, sh_stat, t);

    float4 acc = make_float4(0.f, 0.f, 0.f, 0.f);
#pragma unroll
    for (int i = 0; i < 16; ++i) {
        float yv = sh_y[r0 + i];
        acc.x += yv * wr[i].x; acc.y += yv * wr[i].y;
        acc.z += yv * wr[i].z; acc.w += yv * wr[i].w;
    }
#pragma unroll
    for (int i = 0; i < 16; ++i) wr[i] = W14[(r0 + 16 + i) * 256 + jq];
#pragma unroll
    for (int i = 0; i < 16; ++i) {
        float yv = sh_y[r0 + 16 + i];
        acc.x += yv * wr[i].x; acc.y += yv * wr[i].y;
        acc.z += yv * wr[i].z; acc.w += yv * wr[i].w;
    }
    sh_ps[w * 32 + lane] = acc;
    __syncthreads();
    if (t < 32) {
        float4 a = sh_ps[t];
#pragma unroll
        for (int s = 1; s < 8; ++s) {
            float4 r = sh_ps[s * 32 + t];
            a.x += r.x; a.y += r.y; a.z += r.z; a.w += r.w;
        }
        float4 bb = ((const float4*)bias)[o8 * 32 + t];
        float4 g;
        g.x = gelu_tanh(a.x + bb.x);
        g.y = gelu_tanh(a.y + bb.y);
        g.z = gelu_tanh(a.z + bb.z);
        g.w = gelu_tanh(a.w + bb.w);
        ((float4*)(g_hid + b * HID))[o8 * 32 + t] = g;
    }
}

// ============ K4: h += hid @ w2 + b2.  grid 128 = 16 b x 8 quad-groups ============
__global__ __launch_bounds__(256, 1) void k_mlp_down(
    const float* __restrict__ W, const float* __restrict__ bias)
{
    __shared__ float4 sh_hid4[DD];      // 1024 floats
    __shared__ float4 sh_ps[256];
    __shared__ float4 sh_ps2[64];
    int bk = blockIdx.x, t = threadIdx.x;
    int lane = t & 31, w = t >> 5;
    int b = bk >> 3, g8 = bk & 7;

    const float4* W24 = (const float4*)W;  // [1024 rows][64 quads]
    int q8 = lane & 7, rs = lane >> 3;     // rs 0..3
    int jq = g8 * 8 + q8;
    int r0 = (w * 4 + rs) * 32;            // 32 rows per thread
    float4 wr[16];
#pragma unroll
    for (int i = 0; i < 16; ++i) wr[i] = W24[(r0 + i) * 64 + jq];

    sh_hid4[t] = ((const float4*)(g_hid + b * HID))[t];
    __syncthreads();
    const float* shid = (const float*)sh_hid4;

    float4 acc = make_float4(0.f, 0.f, 0.f, 0.f);
#pragma unroll
    for (int i = 0; i < 16; ++i) {
        float hv = shid[r0 + i];
        acc.x += hv * wr[i].x; acc.y += hv * wr[i].y;
        acc.z += hv * wr[i].z; acc.w += hv * wr[i].w;
    }
#pragma unroll
    for (int i = 0; i < 16; ++i) wr[i] = W24[(r0 + 16 + i) * 64 + jq];
#pragma unroll
    for (int i = 0; i < 16; ++i) {
        float hv = shid[r0 + 16 + i];
        acc.x += hv * wr[i].x; acc.y += hv * wr[i].y;
        acc.z += hv * wr[i].z; acc.w += hv * wr[i].w;
    }
    sh_ps[(w * 4 + rs) * 8 + q8] = acc;    // [32 segs][8 quads]
    __syncthreads();
    if (t < 64) {
        int sub = t >> 3, q = t & 7;
        float4 a = sh_ps[(sub * 4) * 8 + q];
#pragma unroll
        for (int k = 1; k < 4; ++k) {
            float4 r = sh_ps[(sub * 4 + k) * 8 + q];
            a.x += r.x; a.y += r.y; a.z += r.z; a.w += r.w;
        }
        sh_ps2[sub * 8 + q] = a;
    }
    __syncthreads();
    if (t < 8) {
        float4 a = sh_ps2[t];
#pragma unroll
        for (int s = 1; s < 8; ++s) {
            float4 r = sh_ps2[s * 8 + t];
            a.x += r.x; a.y += r.y; a.z += r.z; a.w += r.w;
        }
        float4 bb = ((const float4*)bias)[g8 * 8 + t];
        float4 ho = ((const float4*)(g_h + b * DD))[g8 * 8 + t];
        a.x += bb.x + ho.x; a.y += bb.y + ho.y;
        a.z += bb.z + ho.z; a.w += bb.w + ho.w;
        ((float4*)(g_h + b * DD))[g8 * 8 + t] = a;
    }
}

// ============ head: out[b,c] = h[b] . w_cls[:,c] + b_cls[c] ============
__global__ __launch_bounds__(256, 1) void k_head(
    const float* __restrict__ w_cls, const float* __restrict__ b_cls,
    float* __restrict__ out)
{
    __shared__ float sh_h[DD];
    int b = blockIdx.x, t = threadIdx.x;
    sh_h[t] = g_h[b * DD + t];
    __syncthreads();
    if (t < NC) {
        float acc = b_cls[t];
#pragma unroll 8
        for (int d = 0; d < DD; ++d)
            acc += sh_h[d] * w_cls[d * NC + t];
        out[b * NC + t] = acc;
    }
}

extern "C" void kernel_launch(void* const* d_in, const int* in_sizes, int n_in,
                              void* d_out, int out_size)
{
    // 0:x 1:emb_tok 2:emb_pos 3:proj 4:ln1_s 5:ln1_b 6:wq 7:wk 8:wv 9:wo
    // 10:bo 11:ln2_s 12:ln2_b 13:w1 14:b1 15:w2 16:b2 17:w_cls 18:b_cls
    const int*   x       = (const int*)  d_in[0];
    const float* emb_tok = (const float*)d_in[1];
    const float* emb_pos = (const float*)d_in[2];
    const float* ln1_s   = (const float*)d_in[4];
    const float* ln1_b   = (const float*)d_in[5];
    const float* wv      = (const float*)d_in[8];
    const float* wo      = (const float*)d_in[9];
    const float* bo      = (const float*)d_in[10];
    const float* ln2_s   = (const float*)d_in[11];
    const float* ln2_b   = (const float*)d_in[12];
    const float* w1      = (const float*)d_in[13];
    const float* b1      = (const float*)d_in[14];
    const float* w2      = (const float*)d_in[15];
    const float* b2      = (const float*)d_in[16];
    const float* w_cls   = (const float*)d_in[17];
    const float* b_cls   = (const float*)d_in[18];
    float* out = (float*)d_out;

    for (int l = 0; l < NL; ++l) {
        size_t oDD = (size_t)l * DD * DD;
        k_attn_v<<<64, 256>>>(wv + oDD, ln1_s + l * DD, ln1_b + l * DD,
                              l == 0 ? 1 : 0, x, emb_tok, emb_pos);
        k_attn_o<<<64, 256>>>(wo + oDD, bo + l * DD);
        k_mlp_up<<<128, 256>>>(w1 + (size_t)l * DD * HID, b1 + l * HID,
                               ln2_s + l * DD, ln2_b + l * DD);
        k_mlp_down<<<128, 256>>>(w2 + (size_t)l * HID * DD, b2 + l * DD);
    }
    k_head<<<NB, 256>>>(w_cls, b_cls, out);
}